// round 2
// baseline (speedup 1.0000x reference)
#include <cuda_runtime.h>
#include <cstdint>

// DotPredictor: out[e] = dot(h[src[e]], h[dst[e]]) over D=64 floats.
// Indices are int32 (JAX x64 disabled downcasts int64 -> int32).
// 16 lanes per edge; each lane loads one float4 from each row (coalesced
// 256B per row), 4-step shfl_xor reduction within the 16-lane group.

#define D_FEAT 64
#define VEC_PER_ROW (D_FEAT / 4)   // 16 float4 per row
#define THREADS 256

__global__ __launch_bounds__(THREADS)
void dot_predictor_kernel(const float4* __restrict__ h4,
                          const int* __restrict__ src,
                          const int* __restrict__ dst,
                          float* __restrict__ out,
                          int n_edges)
{
    int tid  = blockIdx.x * THREADS + threadIdx.x;
    int edge = tid >> 4;          // 16 lanes per edge
    int lane = tid & 15;
    if (edge >= n_edges) return;

    // Broadcast loads within the 16-lane group (L1 broadcast, no penalty)
    int s = __ldg(&src[edge]);
    int d = __ldg(&dst[edge]);

    float4 a = __ldg(&h4[(size_t)s * VEC_PER_ROW + lane]);
    float4 b = __ldg(&h4[(size_t)d * VEC_PER_ROW + lane]);

    float p = a.x * b.x + a.y * b.y + a.z * b.z + a.w * b.w;

    // Reduce across the 16-lane group (xor 8/4/2/1 stays within the group)
    p += __shfl_xor_sync(0xFFFFFFFFu, p, 8);
    p += __shfl_xor_sync(0xFFFFFFFFu, p, 4);
    p += __shfl_xor_sync(0xFFFFFFFFu, p, 2);
    p += __shfl_xor_sync(0xFFFFFFFFu, p, 1);

    if (lane == 0) out[edge] = p;
}

extern "C" void kernel_launch(void* const* d_in, const int* in_sizes, int n_in,
                              void* d_out, int out_size)
{
    const float4* h4  = (const float4*)d_in[0];  // h: [N_NODES, 64] f32
    const int*    src = (const int*)d_in[1];     // int32 [E]
    const int*    dst = (const int*)d_in[2];     // int32 [E]
    float*        out = (float*)d_out;           // [E] f32

    int n_edges = in_sizes[1];  // element count of src
    long long total_threads = (long long)n_edges * 16;
    int blocks = (int)((total_threads + THREADS - 1) / THREADS);

    dot_predictor_kernel<<<blocks, THREADS>>>(h4, src, dst, out, n_edges);
}

// round 3
// speedup vs baseline: 1.2454x; 1.2454x over previous
#include <cuda_runtime.h>
#include <cstdint>

// DotPredictor: out[e] = dot(h[src[e]], h[dst[e]]) over D=64 floats.
// 4 lanes per edge; each lane loads 4 float4 from each row (8 independent
// LDG.128 in flight -> MLP=8), 2-step shfl_xor reduction in the 4-lane group.
// Per-instruction access: 4 lanes x 16B = 64B contiguous per row (full
// sectors), so L2 traffic is identical to the 16-lane variant.

#define VEC_PER_ROW 16   // 64 floats = 16 float4 per row
#define THREADS 256

__global__ __launch_bounds__(THREADS)
void dot_predictor_kernel(const float4* __restrict__ h4,
                          const int* __restrict__ src,
                          const int* __restrict__ dst,
                          float* __restrict__ out,
                          int n_edges)
{
    int tid  = blockIdx.x * THREADS + threadIdx.x;
    int edge = tid >> 2;          // 4 lanes per edge
    int lane = tid & 3;
    if (edge >= n_edges) return;

    int s = __ldg(&src[edge]);    // broadcast within 4-lane group
    int d = __ldg(&dst[edge]);

    const float4* pa = h4 + (size_t)s * VEC_PER_ROW + lane;
    const float4* pb = h4 + (size_t)d * VEC_PER_ROW + lane;

    // 8 independent 16B loads per thread
    float4 a0 = __ldg(pa);      float4 b0 = __ldg(pb);
    float4 a1 = __ldg(pa + 4);  float4 b1 = __ldg(pb + 4);
    float4 a2 = __ldg(pa + 8);  float4 b2 = __ldg(pb + 8);
    float4 a3 = __ldg(pa + 12); float4 b3 = __ldg(pb + 12);

    float p = a0.x*b0.x + a0.y*b0.y + a0.z*b0.z + a0.w*b0.w;
    p      += a1.x*b1.x + a1.y*b1.y + a1.z*b1.z + a1.w*b1.w;
    p      += a2.x*b2.x + a2.y*b2.y + a2.z*b2.z + a2.w*b2.w;
    p      += a3.x*b3.x + a3.y*b3.y + a3.z*b3.z + a3.w*b3.w;

    // Reduce across the 4-lane group (xor 2/1 stays inside the group)
    p += __shfl_xor_sync(0xFFFFFFFFu, p, 2);
    p += __shfl_xor_sync(0xFFFFFFFFu, p, 1);

    if (lane == 0) out[edge] = p;
}

extern "C" void kernel_launch(void* const* d_in, const int* in_sizes, int n_in,
                              void* d_out, int out_size)
{
    const float4* h4  = (const float4*)d_in[0];  // h: [N_NODES, 64] f32
    const int*    src = (const int*)d_in[1];     // int32 [E]
    const int*    dst = (const int*)d_in[2];     // int32 [E]
    float*        out = (float*)d_out;           // [E] f32

    int n_edges = in_sizes[1];
    long long total_threads = (long long)n_edges * 4;
    int blocks = (int)((total_threads + THREADS - 1) / THREADS);

    dot_predictor_kernel<<<blocks, THREADS>>>(h4, src, dst, out, n_edges);
}

// round 4
// speedup vs baseline: 1.5391x; 1.2359x over previous
#include <cuda_runtime.h>
#include <cstdint>

// DotPredictor: out[e] = dot(h[src[e]], h[dst[e]]), D=64 f32.
// 8 lanes per edge, 2 edges per thread:
//  - each warp-wide LDG.128 covers 4 rows x 128B contiguous = 4 L1 wavefronts
//    (vs 8 in the 4-lane layout) -> halves L1 wavefronts per edge
//  - 8 independent LDG.128 per thread -> MLP=8
//  - int2 index loads (edges 2g, 2g+1 are contiguous)
//  - 3-step shfl_xor reduction per edge within the 8-lane group

#define VEC_PER_ROW 16   // 16 float4 per 64-float row
#define THREADS 256

__device__ __forceinline__ float dot4(float4 a, float4 b) {
    return a.x*b.x + a.y*b.y + a.z*b.z + a.w*b.w;
}

__global__ __launch_bounds__(THREADS)
void dot_predictor_kernel(const float4* __restrict__ h4,
                          const int2* __restrict__ src2,
                          const int2* __restrict__ dst2,
                          float* __restrict__ out,
                          int n_edges)
{
    int tid   = blockIdx.x * THREADS + threadIdx.x;
    int group = tid >> 3;          // 8 lanes per group; group handles 2 edges
    int lane  = tid & 7;
    int e0    = group * 2;
    if (e0 >= n_edges) return;

    int2 s = __ldg(&src2[group]);  // {src[e0], src[e0+1]}
    int2 d = __ldg(&dst2[group]);

    const float4* pa0 = h4 + (size_t)s.x * VEC_PER_ROW + lane;
    const float4* pb0 = h4 + (size_t)d.x * VEC_PER_ROW + lane;
    const float4* pa1 = h4 + (size_t)s.y * VEC_PER_ROW + lane;
    const float4* pb1 = h4 + (size_t)d.y * VEC_PER_ROW + lane;

    // 8 independent 16B loads (edge e0: 4, edge e0+1: 4)
    float4 a00 = __ldg(pa0);     float4 a01 = __ldg(pa0 + 8);
    float4 b00 = __ldg(pb0);     float4 b01 = __ldg(pb0 + 8);
    float4 a10 = __ldg(pa1);     float4 a11 = __ldg(pa1 + 8);
    float4 b10 = __ldg(pb1);     float4 b11 = __ldg(pb1 + 8);

    float p0 = dot4(a00, b00) + dot4(a01, b01);
    float p1 = dot4(a10, b10) + dot4(a11, b11);

    // Reduce within the 8-lane group (xor 4/2/1)
    p0 += __shfl_xor_sync(0xFFFFFFFFu, p0, 4);
    p1 += __shfl_xor_sync(0xFFFFFFFFu, p1, 4);
    p0 += __shfl_xor_sync(0xFFFFFFFFu, p0, 2);
    p1 += __shfl_xor_sync(0xFFFFFFFFu, p1, 2);
    p0 += __shfl_xor_sync(0xFFFFFFFFu, p0, 1);
    p1 += __shfl_xor_sync(0xFFFFFFFFu, p1, 1);

    if (lane == 0) {
        out[e0] = p0;
        if (e0 + 1 < n_edges) out[e0 + 1] = p1;
    }
}

extern "C" void kernel_launch(void* const* d_in, const int* in_sizes, int n_in,
                              void* d_out, int out_size)
{
    const float4* h4   = (const float4*)d_in[0];  // h: [N_NODES, 64] f32
    const int2*   src2 = (const int2*)d_in[1];    // int32 [E], read as int2
    const int2*   dst2 = (const int2*)d_in[2];
    float*        out  = (float*)d_out;           // [E] f32

    int n_edges = in_sizes[1];
    int n_groups = (n_edges + 1) / 2;              // 2 edges per 8-lane group
    long long total_threads = (long long)n_groups * 8;
    int blocks = (int)((total_threads + THREADS - 1) / THREADS);

    dot_predictor_kernel<<<blocks, THREADS>>>(h4, src2, dst2, out, n_edges);
}